// round 3
// baseline (speedup 1.0000x reference)
#include <cuda_runtime.h>

#define Bb   128
#define DIN  512
#define HH   1024
#define G4   4096
#define TT   256
#define OO   1024
#define BH   (Bb*HH)      // 131072
#define NBLK 128
#define NTHR 256

// ---- device-global scratch (no allocations allowed) ----
__device__ float    g_hs[(TT+1)*BH];     // h history: slot 0 = h0, slot t+1 = h after step t
__device__ float    g_c0[BH];            // initial cell state
__device__ float    g_Wp[G4*HH];         // folded (W_ih+W_hh), block-permuted — for steps t>=1
__device__ float    g_WhhP[G4*HH];       // W_hh only, block-permuted — for step t==0
__device__ float    g_bF[G4];            // folded bias (perm order)
__device__ float    g_b0[G4];            // step-0 bias (perm order, includes x0 @ W_ih^T)
__device__ unsigned g_bar[TT];           // monotonic barrier counters (replay-safe)

__device__ __forceinline__ float sigf(float x) { return 1.0f / (1.0f + __expf(-x)); }

// ---------------------------------------------------------------------------
// Permute + fold weights. Block blk owns 32 rows lr where
// j = blk*8 + (lr&7) + (lr>>3)*1024   (lr&7 = unit, lr>>3 = gate i/f/g/o)
// g_Wp = W_ih + W_hh (for t>=1, where x == h);  g_WhhP = W_hh (for t == 0).
// ---------------------------------------------------------------------------
__global__ void k_fold(const float* __restrict__ Wih, const float* __restrict__ Whh) {
    int i = blockIdx.x * blockDim.x + threadIdx.x;   // float4 index, 1,048,576 total
    int o = i << 2;
    int blk = o >> 15;
    int rem = o & 32767;
    int lr  = rem >> 10;
    int k   = rem & 1023;
    int j   = (blk << 3) + (lr & 7) + ((lr >> 3) << 10);
    float4 a = *(const float4*)(Wih + (size_t)j * HH + k);
    float4 b = *(const float4*)(Whh + (size_t)j * HH + k);
    float4 r;
    r.x = a.x + b.x; r.y = a.y + b.y; r.z = a.z + b.z; r.w = a.w + b.w;
    *(float4*)(g_Wp + o)   = r;
    *(float4*)(g_WhhP + o) = b;
}

// bias fold: g_bF[p] = b_ih[j]+b_hh[j];  g_b0[p] = g_bF[p] + dot(x0, W_ih[j])
__global__ void k_bias(const float* __restrict__ Wih, const float* __restrict__ bih,
                       const float* __restrict__ bhh, const float* __restrict__ x0) {
    int w    = (blockIdx.x * blockDim.x + threadIdx.x) >> 5;
    int lane = threadIdx.x & 31;
    if (w >= G4) return;
    int blk = w >> 5, lr = w & 31;
    int j   = (blk << 3) + (lr & 7) + ((lr >> 3) << 10);
    float s = 0.f;
    for (int k = lane; k < HH; k += 32) s += x0[k] * Wih[(size_t)j * HH + k];
    #pragma unroll
    for (int off = 16; off; off >>= 1) s += __shfl_down_sync(0xffffffffu, s, off);
    if (lane == 0) {
        float bf = bih[j] + bhh[j];
        g_bF[w] = bf;
        g_b0[w] = bf + s;
    }
}

// h0 = z @ W_fc_h^T + b_fc_h  -> g_hs slot 0 ;  c0 -> g_c0.  One warp per (b,u).
__global__ void k_init(const float* __restrict__ z,
                       const float* __restrict__ Wh, const float* __restrict__ bh,
                       const float* __restrict__ Wc, const float* __restrict__ bc) {
    int w    = (blockIdx.x * blockDim.x + threadIdx.x) >> 5;   // 131072 warps
    int lane = threadIdx.x & 31;
    int b = w >> 10, u = w & 1023;
    float sh = 0.f, sc = 0.f;
    for (int k = lane; k < DIN; k += 32) {
        float zv = z[b * DIN + k];
        sh += zv * Wh[u * DIN + k];
        sc += zv * Wc[u * DIN + k];
    }
    #pragma unroll
    for (int off = 16; off; off >>= 1) {
        sh += __shfl_down_sync(0xffffffffu, sh, off);
        sc += __shfl_down_sync(0xffffffffu, sc, off);
    }
    if (lane == 0) {
        g_hs[b * HH + u] = sh + bh[u];
        g_c0[b * HH + u] = sc + bc[u];
    }
}

// ---------------------------------------------------------------------------
// Persistent recurrence: 128 blocks, one grid barrier per step.
// Block blk: computes gates[128 x 32 rows] = h @ W_blk^T, updates its 8 units.
// t==0 uses g_WhhP (x-part already folded into g_b0); t>=1 uses g_Wp.
// smem: h_s[128][65] staging, w_s[32][65], gates gs[32][129], c_s[8][128]
// ---------------------------------------------------------------------------
__global__ void __launch_bounds__(NTHR, 1) k_steps() {
    extern __shared__ float sm[];
    float* h_s = sm;                      // 8320
    float* w_s = sm + 8320;               // 2080
    float* gs  = sm + 8320 + 2080;        // 4128
    float* c_s = sm + 8320 + 2080 + 4128; // 1024
    const int tid = threadIdx.x, blk = blockIdx.x;
    const int tx = tid & 31, ty = tid >> 5;          // tx: batch lane, ty: warp (j group)

    // load block-owned cell state
    for (int i = tid; i < 1024; i += NTHR) {
        int u = i >> 7, b = i & 127;
        c_s[u * 128 + b] = g_c0[b * HH + (blk << 3) + u];
    }
    const float* WbF = g_Wp   + (size_t)blk * 32 * HH;
    const float* Wb0 = g_WhhP + (size_t)blk * 32 * HH;
    __syncthreads();

    for (int t = 0; t < TT; ++t) {
        const float* hp = g_hs + (size_t)t * BH;
        const float* Wb = t ? WbF : Wb0;
        float acc[4][4];
        #pragma unroll
        for (int m = 0; m < 4; ++m)
            #pragma unroll
            for (int j = 0; j < 4; ++j) acc[m][j] = 0.f;

        for (int kc = 0; kc < HH; kc += 64) {
            // stage h chunk [128][64] (L1-bypassed: coherence through barrier)
            {
                int c4 = tid & 15, r0 = tid >> 4;
                #pragma unroll
                for (int p = 0; p < 8; ++p) {
                    int b = r0 + (p << 4);
                    float4 v = __ldcg((const float4*)(hp + b * HH + kc + (c4 << 2)));
                    float* d = h_s + b * 65 + (c4 << 2);
                    d[0] = v.x; d[1] = v.y; d[2] = v.z; d[3] = v.w;
                }
                #pragma unroll
                for (int q = 0; q < 2; ++q) {
                    int idx = tid + (q << 8);
                    int r = idx >> 4, cc = idx & 15;
                    float4 v = *(const float4*)(Wb + r * HH + kc + (cc << 2));
                    float* d = w_s + r * 65 + (cc << 2);
                    d[0] = v.x; d[1] = v.y; d[2] = v.z; d[3] = v.w;
                }
            }
            __syncthreads();
            #pragma unroll
            for (int k = 0; k < 64; ++k) {
                float a[4], w[4];
                #pragma unroll
                for (int m = 0; m < 4; ++m) a[m] = h_s[(tx + (m << 5)) * 65 + k];
                #pragma unroll
                for (int j = 0; j < 4; ++j) w[j] = w_s[((ty << 2) + j) * 65 + k];
                #pragma unroll
                for (int m = 0; m < 4; ++m)
                    #pragma unroll
                    for (int j = 0; j < 4; ++j) acc[m][j] += a[m] * w[j];
            }
            __syncthreads();
        }

        // gates -> smem (+bias; step 0 uses x0-folded bias)
        const float* bias = t ? g_bF : g_b0;
        #pragma unroll
        for (int j = 0; j < 4; ++j) {
            float bv = bias[(blk << 5) + (ty << 2) + j];
            #pragma unroll
            for (int m = 0; m < 4; ++m)
                gs[((ty << 2) + j) * 129 + tx + (m << 5)] = acc[m][j] + bv;
        }
        __syncthreads();

        // elementwise LSTM update for block's 8 units x 128 batch
        float* hn = g_hs + (size_t)(t + 1) * BH;
        #pragma unroll
        for (int i2 = 0; i2 < 4; ++i2) {
            int e = tid + (i2 << 8);
            int b = e >> 3, u = e & 7;
            float ig = gs[u * 129 + b];
            float fg = gs[(u + 8) * 129 + b];
            float gg = gs[(u + 16) * 129 + b];
            float og = gs[(u + 24) * 129 + b];
            float cv = c_s[u * 128 + b];
            float cn = sigf(fg) * cv + sigf(ig) * tanhf(gg);
            float hv = sigf(og) * tanhf(cn);
            c_s[u * 128 + b] = cn;
            hn[b * HH + (blk << 3) + u] = hv;
        }

        // grid barrier (monotonic counter: no reset needed across graph replays)
        __threadfence();
        __syncthreads();
        if (tid == 0) {
            unsigned old    = atomicAdd(&g_bar[t], 1u);
            unsigned target = old - (old & (NBLK - 1)) + NBLK;
            volatile unsigned* p = &g_bar[t];
            while ((int)(*p - target) < 0) { }
        }
        __syncthreads();
    }
}

// ---------------------------------------------------------------------------
// out[b,t,o] = leaky( hs[t+1][b] . W_out[o] + b_out[o] )
// A = g_hs + BH viewed as [32768][1024] row-major (m = t*128+b).
// 64x64 tile, BK=32, 256 threads, 4x4 per thread; smem-staged coalesced store.
// ---------------------------------------------------------------------------
__global__ void __launch_bounds__(256) k_out(const float* __restrict__ Wout,
                                             const float* __restrict__ bout,
                                             float* __restrict__ out) {
    __shared__ float A_s[64 * 33];
    __shared__ float B_s[64 * 33];
    __shared__ float C_s[64 * 68];
    const float* A = g_hs + BH;
    const int tid = threadIdx.x;
    const int tx = tid & 15, ty = tid >> 4;
    const int m0 = blockIdx.x * 64, o0 = blockIdx.y * 64;

    float acc[4][4];
    #pragma unroll
    for (int m = 0; m < 4; ++m)
        #pragma unroll
        for (int o = 0; o < 4; ++o) acc[m][o] = 0.f;

    for (int kc = 0; kc < HH; kc += 32) {
        #pragma unroll
        for (int q = 0; q < 2; ++q) {
            int idx = tid + (q << 8);          // 0..511
            int r = idx >> 3, c4 = idx & 7;
            float4 va = *(const float4*)(A + (size_t)(m0 + r) * HH + kc + (c4 << 2));
            float* da = A_s + r * 33 + (c4 << 2);
            da[0] = va.x; da[1] = va.y; da[2] = va.z; da[3] = va.w;
            float4 vb = *(const float4*)(Wout + (size_t)(o0 + r) * HH + kc + (c4 << 2));
            float* db = B_s + r * 33 + (c4 << 2);
            db[0] = vb.x; db[1] = vb.y; db[2] = vb.z; db[3] = vb.w;
        }
        __syncthreads();
        #pragma unroll
        for (int k = 0; k < 32; ++k) {
            float a[4], w[4];
            #pragma unroll
            for (int m = 0; m < 4; ++m) a[m] = A_s[(tx + (m << 4)) * 33 + k];
            #pragma unroll
            for (int o = 0; o < 4; ++o) w[o] = B_s[(ty + (o << 4)) * 33 + k];
            #pragma unroll
            for (int m = 0; m < 4; ++m)
                #pragma unroll
                for (int o = 0; o < 4; ++o) acc[m][o] += a[m] * w[o];
        }
        __syncthreads();
    }

    // stage C tile then write coalesced (64 consecutive o per row)
    #pragma unroll
    for (int m = 0; m < 4; ++m)
        #pragma unroll
        for (int o = 0; o < 4; ++o)
            C_s[(tx + (m << 4)) * 68 + ty + (o << 4)] = acc[m][o];
    __syncthreads();

    #pragma unroll
    for (int q = 0; q < 4; ++q) {
        int idx = tid + (q << 8);              // 0..1023
        int r = idx >> 4, c4 = idx & 15;
        int m = m0 + r;
        int t = m >> 7, b = m & 127;
        const float* cp = C_s + r * 68 + (c4 << 2);
        float4 v;
        float bo0 = bout[o0 + (c4 << 2) + 0];
        float bo1 = bout[o0 + (c4 << 2) + 1];
        float bo2 = bout[o0 + (c4 << 2) + 2];
        float bo3 = bout[o0 + (c4 << 2) + 3];
        float x0v = cp[0] + bo0, x1 = cp[1] + bo1, x2 = cp[2] + bo2, x3 = cp[3] + bo3;
        v.x = x0v >= 0.f ? x0v : 0.2f * x0v;
        v.y = x1  >= 0.f ? x1  : 0.2f * x1;
        v.z = x2  >= 0.f ? x2  : 0.2f * x2;
        v.w = x3  >= 0.f ? x3  : 0.2f * x3;
        *(float4*)(out + (size_t)b * (TT * OO) + (size_t)t * OO + o0 + (c4 << 2)) = v;
    }
}

// ---------------------------------------------------------------------------
extern "C" void kernel_launch(void* const* d_in, const int* in_sizes, int n_in,
                              void* d_out, int out_size) {
    const float* z      = (const float*)d_in[0];
    // d_in[1] = sequence_length (256), compile-time constant here
    const float* W_fc_h = (const float*)d_in[2];
    const float* b_fc_h = (const float*)d_in[3];
    const float* W_fc_c = (const float*)d_in[4];
    const float* b_fc_c = (const float*)d_in[5];
    const float* W_ih   = (const float*)d_in[6];
    const float* b_ih   = (const float*)d_in[7];
    const float* W_hh   = (const float*)d_in[8];
    const float* b_hh   = (const float*)d_in[9];
    const float* x0     = (const float*)d_in[10];
    const float* W_out  = (const float*)d_in[11];
    const float* b_out  = (const float*)d_in[12];
    float* out = (float*)d_out;

    k_fold<<<4096, 256>>>(W_ih, W_hh);
    k_bias<<<512, 256>>>(W_ih, b_ih, b_hh, x0);
    k_init<<<16384, 256>>>(z, W_fc_h, b_fc_h, W_fc_c, b_fc_c);

    const int SMEM = (8320 + 2080 + 4128 + 1024) * (int)sizeof(float);  // 62208 B
    cudaFuncSetAttribute(k_steps, cudaFuncAttributeMaxDynamicSharedMemorySize, SMEM);
    k_steps<<<NBLK, NTHR, SMEM>>>();

    k_out<<<dim3(512, 16), 256>>>(W_out, b_out, out);
}

// round 8
// speedup vs baseline: 1.3181x; 1.3181x over previous
#include <cuda_runtime.h>
#include <cuda_bf16.h>

#define Bb   128
#define DIN  512
#define HH   1024
#define G4   4096
#define TT   256
#define OO   1024
#define BH   (Bb*HH)      // 131072
#define NBLK 128
#define NTHR 256

// ---- device-global scratch ----
__device__ __align__(16) unsigned      g_hpk[(TT+1)*BH];     // packed (hi | lo<<16) bf16 h history
__device__ __align__(16) float         g_c0[BH];             // initial cell state
__device__ __align__(16) unsigned char g_WswF[NBLK*131072];  // folded slices (t>=1), tile layout
__device__ __align__(16) unsigned char g_Wsw0[NBLK*131072];  // W_hh slices (t==0), tile layout
__device__ __align__(16) unsigned char g_WoT[16*16*16384];   // W_out tiles [nb][ch][split][ck4][16x128B]
__device__ float    g_bF[G4];
__device__ float    g_b0[G4];
__device__ unsigned g_bar[TT];                               // monotonic barrier counters

__device__ __forceinline__ float sigf(float x) { return 1.0f / (1.0f + __expf(-x)); }

__device__ __forceinline__ unsigned pk_split(float v) {
    __nv_bfloat16 hi = __float2bfloat16(v);
    __nv_bfloat16 lo = __float2bfloat16(v - __bfloat162float(hi));
    return (unsigned)__bfloat16_as_ushort(hi) | ((unsigned)__bfloat16_as_ushort(lo) << 16);
}

__device__ __forceinline__ unsigned smem_u32(const void* p) {
    return (unsigned)__cvta_generic_to_shared(p);
}
__device__ __forceinline__ void ldsm4(unsigned* r, unsigned addr) {
    asm volatile("ldmatrix.sync.aligned.m8n8.x4.shared.b16 {%0,%1,%2,%3}, [%4];"
                 : "=r"(r[0]), "=r"(r[1]), "=r"(r[2]), "=r"(r[3]) : "r"(addr));
}
__device__ __forceinline__ void mma16816(float* d, const unsigned* a, const unsigned* b) {
    asm volatile("mma.sync.aligned.m16n8k16.row.col.f32.bf16.bf16.f32 "
                 "{%0,%1,%2,%3}, {%4,%5,%6,%7}, {%8,%9}, {%0,%1,%2,%3};"
                 : "+f"(d[0]), "+f"(d[1]), "+f"(d[2]), "+f"(d[3])
                 : "r"(a[0]), "r"(a[1]), "r"(a[2]), "r"(a[3]), "r"(b[0]), "r"(b[1]));
}

// ---------------------------------------------------------------------------
// k_foldw: permute + fold weights into per-block slice tiles (ldmatrix-native).
// Slice row rr (0..31): gate=rr>>3, unit=rr&7 -> j = gate*1024 + blk*8 + unit.
// Tile layout per split (64KB): off = (k>>4)*1024 + ((gate*2)+((k>>3)&1))*128
//                                     + unit*16 + (k&7)*2
// ---------------------------------------------------------------------------
__global__ void k_foldw(const float* __restrict__ Wih, const float* __restrict__ Whh) {
    int i = blockIdx.x * blockDim.x + threadIdx.x;   // 4,194,304
    int k = i & 1023, rr = (i >> 10) & 31, blk = i >> 15;
    int gate = rr >> 3, unit = rr & 7;
    int j = (gate << 10) + (blk << 3) + unit;
    float a = Wih[(size_t)j * HH + k];
    float b = Whh[(size_t)j * HH + k];
    float f = a + b;
    int off = ((k >> 4) << 10) + (((gate << 1) + ((k >> 3) & 1)) << 7) + (unit << 4) + ((k & 7) << 1);
    unsigned char* bF = g_WswF + (size_t)blk * 131072;
    unsigned char* b0 = g_Wsw0 + (size_t)blk * 131072;
    __nv_bfloat16 fh = __float2bfloat16(f);
    __nv_bfloat16 fl = __float2bfloat16(f - __bfloat162float(fh));
    *(__nv_bfloat16*)(bF + off)         = fh;
    *(__nv_bfloat16*)(bF + 65536 + off) = fl;
    __nv_bfloat16 wh = __float2bfloat16(b);
    __nv_bfloat16 wl = __float2bfloat16(b - __bfloat162float(wh));
    *(__nv_bfloat16*)(b0 + off)         = wh;
    *(__nv_bfloat16*)(b0 + 65536 + off) = wl;
}

// W_out -> [nb(16)][ch(16)] 16KB blocks: [split(2)][ck4(4)][nt*2+kt tiles 16x128B]
__global__ void k_foldo(const float* __restrict__ Wout) {
    int i = blockIdx.x * blockDim.x + threadIdx.x;   // 1,048,576
    int k = i & 1023, o = i >> 10;
    int nb = o >> 6, nt = (o >> 3) & 7, r = o & 7;
    int ch = k >> 6, ck4 = (k >> 4) & 3, kt = (k >> 3) & 1, c = k & 7;
    unsigned char* base = g_WoT + (size_t)(nb * 16 + ch) * 16384;
    int toff = (ck4 << 11) + (((nt << 1) + kt) << 7) + (r << 4) + (c << 1);
    float w = Wout[(size_t)o * HH + k];
    __nv_bfloat16 hi = __float2bfloat16(w);
    __nv_bfloat16 lo = __float2bfloat16(w - __bfloat162float(hi));
    *(__nv_bfloat16*)(base + toff)        = hi;
    *(__nv_bfloat16*)(base + 8192 + toff) = lo;
}

// bias fold (perm order r = gate*8+unit per blk)
__global__ void k_bias(const float* __restrict__ Wih, const float* __restrict__ bih,
                       const float* __restrict__ bhh, const float* __restrict__ x0) {
    int w    = (blockIdx.x * blockDim.x + threadIdx.x) >> 5;
    int lane = threadIdx.x & 31;
    if (w >= G4) return;
    int blk = w >> 5, lr = w & 31;
    int j   = (blk << 3) + (lr & 7) + ((lr >> 3) << 10);
    float s = 0.f;
    for (int k = lane; k < HH; k += 32) s += x0[k] * Wih[(size_t)j * HH + k];
    #pragma unroll
    for (int off = 16; off; off >>= 1) s += __shfl_down_sync(0xffffffffu, s, off);
    if (lane == 0) {
        float bf = bih[j] + bhh[j];
        g_bF[w] = bf;
        g_b0[w] = bf + s;
    }
}

// h0 (packed bf16 split) -> g_hpk slot 0 ; c0 -> g_c0
__global__ void k_init(const float* __restrict__ z,
                       const float* __restrict__ Wh, const float* __restrict__ bh,
                       const float* __restrict__ Wc, const float* __restrict__ bc) {
    int w    = (blockIdx.x * blockDim.x + threadIdx.x) >> 5;
    int lane = threadIdx.x & 31;
    int b = w >> 10, u = w & 1023;
    float sh = 0.f, sc = 0.f;
    for (int k = lane; k < DIN; k += 32) {
        float zv = z[b * DIN + k];
        sh += zv * Wh[u * DIN + k];
        sc += zv * Wc[u * DIN + k];
    }
    #pragma unroll
    for (int off = 16; off; off >>= 1) {
        sh += __shfl_down_sync(0xffffffffu, sh, off);
        sc += __shfl_down_sync(0xffffffffu, sc, off);
    }
    if (lane == 0) {
        g_hpk[b * HH + u] = pk_split(sh + bh[u]);
        g_c0[b * HH + u]  = sc + bc[u];
    }
}

// ---------------------------------------------------------------------------
// Persistent HMMA recurrence. 128 CTAs x 8 warps. W slice resident in SMEM.
// SMEM: [0..128) b0s, [128..256) bFs | 1024: W_hi (64K), 66560: W_lo (64K)
//       A bufs: 132096/148480 (buf0 hi/lo), 164864/181248 (buf1 hi/lo)
// ---------------------------------------------------------------------------
#define S_WHI 1024
#define S_WLO 66560
#define A0H 132096
#define A0L 148480
#define A1H 164864
#define A1L 181248
#define S_TOT 197632

__global__ void __launch_bounds__(NTHR, 1) k_steps_mma() {
    extern __shared__ unsigned char sm[];
    const unsigned sb = smem_u32(sm);
    const int tid = threadIdx.x, blk = blockIdx.x;
    const int w = tid >> 5, lane = tid & 31;
    const int q = lane & 3, gr = lane >> 2, ls = lane >> 3;
    float* b0s = (float*)(sm);
    float* bFs = (float*)(sm + 128);

    if (tid < 32) {
        b0s[tid] = g_b0[blk * 32 + tid];
        bFs[tid] = g_bF[blk * 32 + tid];
    }
    {   // W slices for step 0 (W_hh only)
        const uint4* src = (const uint4*)(g_Wsw0 + (size_t)blk * 131072);
        uint4* dst = (uint4*)(sm + S_WHI);
        for (int i = tid; i < 8192; i += NTHR) dst[i] = src[i];
    }
    // cell state in registers: thread owns (m, m+8) x (2q, 2q+1)
    float cst[2][2];
    {
        int m0 = (w << 4) + gr;
        float2 v0 = *(const float2*)(g_c0 + m0 * HH + (blk << 3) + (q << 1));
        float2 v1 = *(const float2*)(g_c0 + (m0 + 8) * HH + (blk << 3) + (q << 1));
        cst[0][0] = v0.x; cst[0][1] = v0.y;
        cst[1][0] = v1.x; cst[1][1] = v1.y;
    }
    __syncthreads();

    // per-thread ldmatrix base offsets
    const unsigned aBase = (unsigned)(((w * 2 + (ls & 1)) * 8 + (ls >> 1)) * 128 + (lane & 7) * 16);
    const unsigned bBase = (unsigned)((((ls >> 1) * 2 + (ls & 1)) * 128) + (lane & 7) * 16);
    // staging mapping: row = p*16 + (tid&15), c0 = (tid>>4)*4
    const int srow = tid & 15;
    const int kc4  = tid >> 4;            // c0>>2
    const int c0   = kc4 << 2;
    const int sOff = ((srow >> 3) * 8 + (c0 >> 3)) * 128 + (srow & 7) * 16 + ((c0 & 7) << 1);

    for (int t = 0; t < TT; ++t) {
        const uint4* hp4 = (const uint4*)(g_hpk + (size_t)t * BH);
        float acc[4][4];
        #pragma unroll
        for (int a = 0; a < 4; ++a)
            #pragma unroll
            for (int b = 0; b < 4; ++b) acc[a][b] = 0.f;

        uint4 pre[8];
        #pragma unroll
        for (int p = 0; p < 8; ++p)
            pre[p] = __ldcg(hp4 + p * 4096 + srow * 256 + kc4);
        // stage chunk 0 -> buf0
        #pragma unroll
        for (int p = 0; p < 8; ++p) {
            uint4 v = pre[p];
            unsigned h0 = __byte_perm(v.x, v.y, 0x5410), l0 = __byte_perm(v.x, v.y, 0x7632);
            unsigned h1 = __byte_perm(v.z, v.w, 0x5410), l1 = __byte_perm(v.z, v.w, 0x7632);
            int off = p * 2048 + sOff;
            *(uint2*)(sm + A0H + off) = make_uint2(h0, h1);
            *(uint2*)(sm + A0L + off) = make_uint2(l0, l1);
        }
        __syncthreads();

        for (int ch = 0; ch < 16; ++ch) {
            int buf = ch & 1;
            if (ch < 15) {
                #pragma unroll
                for (int p = 0; p < 8; ++p)
                    pre[p] = __ldcg(hp4 + p * 4096 + srow * 256 + (ch + 1) * 16 + kc4);
            }
            unsigned Abh = sb + (buf ? A1H : A0H);
            unsigned Abl = sb + (buf ? A1L : A0L);
            #pragma unroll
            for (int kk = 0; kk < 4; ++kk) {
                unsigned Ah[4], Al[4];
                ldsm4(Ah, Abh + aBase + kk * 256);
                ldsm4(Al, Abl + aBase + kk * 256);
                int ck = ch * 4 + kk;
                #pragma unroll
                for (int gg = 0; gg < 2; ++gg) {
                    unsigned Bh[4], Bl[4];
                    ldsm4(Bh, sb + S_WHI + ck * 1024 + gg * 512 + bBase);
                    ldsm4(Bl, sb + S_WLO + ck * 1024 + gg * 512 + bBase);
                    mma16816(acc[2 * gg],     Ah, Bh);
                    mma16816(acc[2 * gg],     Ah, Bl);
                    mma16816(acc[2 * gg],     Al, Bh);
                    mma16816(acc[2 * gg + 1], Ah, Bh + 2);
                    mma16816(acc[2 * gg + 1], Ah, Bl + 2);
                    mma16816(acc[2 * gg + 1], Al, Bh + 2);
                }
            }
            if (ch < 15) {   // stage prefetched chunk -> other buf
                unsigned hb = buf ? A0H : A1H, lb = buf ? A0L : A1L;
                #pragma unroll
                for (int p = 0; p < 8; ++p) {
                    uint4 v = pre[p];
                    unsigned h0 = __byte_perm(v.x, v.y, 0x5410), l0 = __byte_perm(v.x, v.y, 0x7632);
                    unsigned h1 = __byte_perm(v.z, v.w, 0x5410), l1 = __byte_perm(v.z, v.w, 0x7632);
                    int off = p * 2048 + sOff;
                    *(uint2*)(sm + hb + off) = make_uint2(h0, h1);
                    *(uint2*)(sm + lb + off) = make_uint2(l0, l1);
                }
            }
            __syncthreads();
        }

        // epilogue: 4 gates of (m, u) live in this thread — no shuffles
        const float* bs = t ? bFs : b0s;
        unsigned* hn = g_hpk + (size_t)(t + 1) * BH;
        #pragma unroll
        for (int r = 0; r < 2; ++r) {
            int m = (w << 4) + gr + (r << 3);
            unsigned pk2[2];
            #pragma unroll
            for (int s = 0; s < 2; ++s) {
                int u = (q << 1) + s;
                int fi = r * 2 + s;
                float ig = acc[0][fi] + bs[u];
                float fg = acc[1][fi] + bs[8 + u];
                float gg = acc[2][fi] + bs[16 + u];
                float og = acc[3][fi] + bs[24 + u];
                float cn = sigf(fg) * cst[r][s] + sigf(ig) * tanhf(gg);
                cst[r][s] = cn;
                pk2[s] = pk_split(sigf(og) * tanhf(cn));
            }
            *(uint2*)(hn + m * HH + (blk << 3) + (q << 1)) = make_uint2(pk2[0], pk2[1]);
        }

        if (t == 0) {   // swap in folded weights for steps >= 1
            __syncthreads();
            const uint4* src = (const uint4*)(g_WswF + (size_t)blk * 131072);
            uint4* dst = (uint4*)(sm + S_WHI);
            for (int i = tid; i < 8192; i += NTHR) dst[i] = src[i];
        }

        __threadfence();
        __syncthreads();
        if (tid == 0) {
            unsigned old    = atomicAdd(&g_bar[t], 1u);
            unsigned target = old - (old & (NBLK - 1)) + NBLK;
            volatile unsigned* p = &g_bar[t];
            while ((int)(*p - target) < 0) { }
        }
        __syncthreads();
    }
}

// ---------------------------------------------------------------------------
// Output GEMM: out[b,t,o] = leaky(hs . W_out^T + b_out). M=32768,N=1024,K=1024.
// 128x64 tiles, HMMA 3-split. grid(16 nb, 256 mb), 256 thr, occupancy 2.
// SMEM: bias 0..256 | A: 1024/17408 (b0 hi/lo), 33792/50176 (b1) | B: 66560/82944
// ---------------------------------------------------------------------------
#define OB_A0H 1024
#define OB_A0L 17408
#define OB_A1H 33792
#define OB_A1L 50176
#define OB_B0  66560
#define OB_B1  82944
#define SO_TOT 99328

__global__ void __launch_bounds__(256, 2) k_out_mma(const float* __restrict__ bout,
                                                    float* __restrict__ out) {
    extern __shared__ unsigned char sm[];
    const unsigned sb = smem_u32(sm);
    const int tid = threadIdx.x;
    const int w = tid >> 5, lane = tid & 31;
    const int q = lane & 3, gr = lane >> 2, ls = lane >> 3;
    const int nb = blockIdx.x, mb = blockIdx.y;
    float* bias_s = (float*)(sm);
    if (tid < 64) bias_s[tid] = bout[nb * 64 + tid];
    __syncthreads();

    const unsigned aBase = (unsigned)(((w * 2 + (ls & 1)) * 8 + (ls >> 1)) * 128 + (lane & 7) * 16);
    const unsigned bBase = (unsigned)((((ls >> 1) * 2 + (ls & 1)) * 128) + (lane & 7) * 16);
    const int srow = tid & 15;
    const int kc4  = tid >> 4;
    const int c0   = kc4 << 2;
    const int sOff = ((srow >> 3) * 8 + (c0 >> 3)) * 128 + (srow & 7) * 16 + ((c0 & 7) << 1);

    const uint4* A4 = (const uint4*)(g_hpk + BH) + (size_t)(mb * 128) * 256;
    const uint4* B4 = (const uint4*)g_WoT + (size_t)nb * 16384;

    float acc[8][4];
    #pragma unroll
    for (int a = 0; a < 8; ++a)
        #pragma unroll
        for (int b = 0; b < 4; ++b) acc[a][b] = 0.f;

    uint4 preA[8], preB[4];
    #pragma unroll
    for (int p = 0; p < 8; ++p) preA[p] = __ldcg(A4 + p * 4096 + srow * 256 + kc4);
    #pragma unroll
    for (int j = 0; j < 4; ++j) preB[j] = __ldcg(B4 + tid + j * 256);
    // stage chunk 0 -> buf0
    #pragma unroll
    for (int p = 0; p < 8; ++p) {
        uint4 v = preA[p];
        unsigned h0 = __byte_perm(v.x, v.y, 0x5410), l0 = __byte_perm(v.x, v.y, 0x7632);
        unsigned h1 = __byte_perm(v.z, v.w, 0x5410), l1 = __byte_perm(v.z, v.w, 0x7632);
        int off = p * 2048 + sOff;
        *(uint2*)(sm + OB_A0H + off) = make_uint2(h0, h1);
        *(uint2*)(sm + OB_A0L + off) = make_uint2(l0, l1);
    }
    #pragma unroll
    for (int j = 0; j < 4; ++j) ((uint4*)(sm + OB_B0))[tid + j * 256] = preB[j];
    __syncthreads();

    for (int ch = 0; ch < 16; ++ch) {
        int buf = ch & 1;
        if (ch < 15) {
            #pragma unroll
            for (int p = 0; p < 8; ++p)
                preA[p] = __ldcg(A4 + p * 4096 + srow * 256 + (ch + 1) * 16 + kc4);
            #pragma unroll
            for (int j = 0; j < 4; ++j)
                preB[j] = __ldcg(B4 + (ch + 1) * 1024 + tid + j * 256);
        }
        unsigned Abh  = sb + (buf ? OB_A1H : OB_A0H);
        unsigned Abl  = sb + (buf ? OB_A1L : OB_A0L);
        unsigned Bsel = sb + (buf ? OB_B1  : OB_B0);
        #pragma unroll
        for (int kk = 0; kk < 4; ++kk) {
            unsigned Ah[4], Al[4];
            ldsm4(Ah, Abh + aBase + kk * 256);
            ldsm4(Al, Abl + aBase + kk * 256);
            #pragma unroll
            for (int gg = 0; gg < 4; ++gg) {
                unsigned Bh[4], Bl[4];
                ldsm4(Bh, Bsel + kk * 2048 + gg * 512 + bBase);          // split 0 (hi)
                ldsm4(Bl, Bsel + 8192 + kk * 2048 + gg * 512 + bBase);   // split 1 (lo)
                mma16816(acc[2 * gg],     Ah, Bh);
                mma16816(acc[2 * gg],     Ah, Bl);
                mma16816(acc[2 * gg],     Al, Bh);
                mma16816(acc[2 * gg + 1], Ah, Bh + 2);
                mma16816(acc[2 * gg + 1], Ah, Bl + 2);
                mma16816(acc[2 * gg + 1], Al, Bh + 2);
            }
        }
        if (ch < 15) {
            unsigned hb = buf ? OB_A0H : OB_A1H, lb = buf ? OB_A0L : OB_A1L;
            unsigned bb = buf ? OB_B0 : OB_B1;
            #pragma unroll
            for (int p = 0; p < 8; ++p) {
                uint4 v = preA[p];
                unsigned h0 = __byte_perm(v.x, v.y, 0x5410), l0 = __byte_perm(v.x, v.y, 0x7632);
                unsigned h1 = __byte_perm(v.z, v.w, 0x5410), l1 = __byte_perm(v.z, v.w, 0x7632);
                int off = p * 2048 + sOff;
                *(uint2*)(sm + hb + off) = make_uint2(h0, h1);
                *(uint2*)(sm + lb + off) = make_uint2(l0, l1);
            }
            #pragma unroll
            for (int j = 0; j < 4; ++j) ((uint4*)(sm + bb))[tid + j * 256] = preB[j];
        }
        __syncthreads();
    }

    // epilogue: bias + LeakyReLU, float2 stores
    #pragma unroll
    for (int nt = 0; nt < 8; ++nt) {
        int o0 = nb * 64 + nt * 8 + (q << 1);
        float bo0 = bias_s[nt * 8 + (q << 1)];
        float bo1 = bias_s[nt * 8 + (q << 1) + 1];
        #pragma unroll
        for (int r = 0; r < 2; ++r) {
            int m = mb * 128 + (w << 4) + gr + (r << 3);
            int tt = m >> 7, b = m & 127;
            float x0 = acc[nt][r * 2]     + bo0;
            float x1 = acc[nt][r * 2 + 1] + bo1;
            float2 v;
            v.x = x0 >= 0.f ? x0 : 0.2f * x0;
            v.y = x1 >= 0.f ? x1 : 0.2f * x1;
            *(float2*)(out + (size_t)b * (TT * OO) + (size_t)tt * OO + o0) = v;
        }
    }
}

// ---------------------------------------------------------------------------
extern "C" void kernel_launch(void* const* d_in, const int* in_sizes, int n_in,
                              void* d_out, int out_size) {
    const float* z      = (const float*)d_in[0];
    const float* W_fc_h = (const float*)d_in[2];
    const float* b_fc_h = (const float*)d_in[3];
    const float* W_fc_c = (const float*)d_in[4];
    const float* b_fc_c = (const float*)d_in[5];
    const float* W_ih   = (const float*)d_in[6];
    const float* b_ih   = (const float*)d_in[7];
    const float* W_hh   = (const float*)d_in[8];
    const float* b_hh   = (const float*)d_in[9];
    const float* x0     = (const float*)d_in[10];
    const float* W_out  = (const float*)d_in[11];
    const float* b_out  = (const float*)d_in[12];
    float* out = (float*)d_out;

    k_foldw<<<16384, 256>>>(W_ih, W_hh);
    k_foldo<<<4096, 256>>>(W_out);
    k_bias<<<512, 256>>>(W_ih, b_ih, b_hh, x0);
    k_init<<<16384, 256>>>(z, W_fc_h, b_fc_h, W_fc_c, b_fc_c);

    cudaFuncSetAttribute(k_steps_mma, cudaFuncAttributeMaxDynamicSharedMemorySize, S_TOT);
    k_steps_mma<<<NBLK, NTHR, S_TOT>>>();

    cudaFuncSetAttribute(k_out_mma, cudaFuncAttributeMaxDynamicSharedMemorySize, SO_TOT);
    k_out_mma<<<dim3(16, 256), 256, SO_TOT>>>(b_out, out);
}